// round 2
// baseline (speedup 1.0000x reference)
#include <cuda_runtime.h>
#include <cstdint>
#include <cstdio>

// ---------------------------------------------------------------------------
// Stochastic_encoder (VGAE GCN encoder), fp32 baseline.
//   deg/dinv -> t1 = x@W1 (epilogue: ts1 = t1*dinv, out1 = ts1*dinv + b1)
//   scatter edges: out1[dst] += ts1[src]*dinv[dst]
//   h = relu(out1)  (fused into next GEMM's A load)
//   mu / logstd: same pattern with W_mu / W_ls, writing directly into d_out.
// Scratch lives in __device__ globals (no allocation).
// ---------------------------------------------------------------------------

#define NMAX 50176
#define HDIM 128

__device__ float g_deg [NMAX];
__device__ float g_dinv[NMAX];
__device__ float g_ts1 [(size_t)NMAX * HDIM];
__device__ float g_out1[(size_t)NMAX * HDIM];
__device__ float g_ts2 [(size_t)NMAX * 2 * HDIM];

// ---------------------------------------------------------------------------

__global__ void k_zero(float* __restrict__ p, int n) {
    int i = blockIdx.x * blockDim.x + threadIdx.x;
    if (i < n) p[i] = 0.0f;
}

__global__ void k_count(const int* __restrict__ dst, float* __restrict__ deg, int E) {
    int i = blockIdx.x * blockDim.x + threadIdx.x;
    if (i < E) atomicAdd(&deg[dst[i]], 1.0f);
}

__global__ void k_dinv(const float* __restrict__ deg, float* __restrict__ dinv, int n) {
    int i = blockIdx.x * blockDim.x + threadIdx.x;
    if (i < n) dinv[i] = rsqrtf(deg[i] + 1.0f);
}

// ---------------------------------------------------------------------------
// Tiled SGEMM: C[N,128] = A[N,K] @ W[K,128]
// Epilogue: ts[r,c]    = C[r,c] * dinv[r]
//           oinit[r,c] = ts[r,c] * dinv[r] + bias[c]   (self-loop + bias)
// Optional relu on the A operand (layer-1 activation).
// BM=128, BN=128, BK=32, 256 threads, 8x8 micro-tile.
// ---------------------------------------------------------------------------
__global__ __launch_bounds__(256, 2)
void k_gemm128(const float* __restrict__ A, const float* __restrict__ W,
               const float* __restrict__ bias, const float* __restrict__ dinv,
               float* __restrict__ ts, float* __restrict__ oinit,
               int N, int K, int reluA)
{
    __shared__ float As[32][129];   // +1 pad: conflict-free transposed stores
    __shared__ float Bs[32][128];

    const int tid  = threadIdx.x;
    const int tx   = tid & 15;      // 16 col-groups
    const int ty   = tid >> 4;      // 16 row-groups
    const int row0 = blockIdx.x * 128;

    float acc[8][8];
    #pragma unroll
    for (int i = 0; i < 8; i++)
        #pragma unroll
        for (int j = 0; j < 8; j++) acc[i][j] = 0.0f;

    for (int k0 = 0; k0 < K; k0 += 32) {
        // --- load A tile (128 x 32), transposed into As[k][m] ---
        {
            const int c  = tid & 7;     // float4 index within 32 cols
            const int m0 = tid >> 3;    // row 0..31
            #pragma unroll
            for (int p = 0; p < 4; p++) {
                int m = m0 + 32 * p;
                int r = row0 + m;
                float4 v = make_float4(0.f, 0.f, 0.f, 0.f);
                if (r < N)
                    v = *(const float4*)(A + (size_t)r * K + (k0 + c * 4));
                if (reluA) {
                    v.x = fmaxf(v.x, 0.f); v.y = fmaxf(v.y, 0.f);
                    v.z = fmaxf(v.z, 0.f); v.w = fmaxf(v.w, 0.f);
                }
                As[c * 4 + 0][m] = v.x;
                As[c * 4 + 1][m] = v.y;
                As[c * 4 + 2][m] = v.z;
                As[c * 4 + 3][m] = v.w;
            }
        }
        // --- load W tile (32 x 128) ---
        {
            const int cb  = tid & 31;   // float4 col index (32 per row)
            const int kr0 = tid >> 5;   // k-row 0..7
            #pragma unroll
            for (int p = 0; p < 4; p++) {
                int kr = kr0 + 8 * p;
                *(float4*)&Bs[kr][cb * 4] =
                    *(const float4*)(W + (size_t)(k0 + kr) * 128 + cb * 4);
            }
        }
        __syncthreads();

        #pragma unroll
        for (int kk = 0; kk < 32; kk++) {
            float a[8], b[8];
            #pragma unroll
            for (int i = 0; i < 8; i++) a[i] = As[kk][ty * 8 + i];
            float4 b0 = *(float4*)&Bs[kk][tx * 8];
            float4 b1 = *(float4*)&Bs[kk][tx * 8 + 4];
            b[0] = b0.x; b[1] = b0.y; b[2] = b0.z; b[3] = b0.w;
            b[4] = b1.x; b[5] = b1.y; b[6] = b1.z; b[7] = b1.w;
            #pragma unroll
            for (int i = 0; i < 8; i++)
                #pragma unroll
                for (int j = 0; j < 8; j++)
                    acc[i][j] = fmaf(a[i], b[j], acc[i][j]);
        }
        __syncthreads();
    }

    // --- epilogue ---
    #pragma unroll
    for (int i = 0; i < 8; i++) {
        int r = row0 + ty * 8 + i;
        if (r < N) {
            float di = dinv[r];
            #pragma unroll
            for (int j = 0; j < 8; j++) {
                int c = tx * 8 + j;
                float t = acc[i][j] * di;
                ts   [(size_t)r * 128 + c] = t;
                oinit[(size_t)r * 128 + c] = fmaf(t, di, bias[c]);
            }
        }
    }
}

// ---------------------------------------------------------------------------
// Edge scatter: one warp per edge.
//   out[dst, :] += ts[src, :] * dinv[dst]      (ts already carries dinv[src])
// Vector reduction (red.global.add.v4.f32) — no return value, L2-side RMW.
// ---------------------------------------------------------------------------
__global__ void k_scatter(const float* __restrict__ ts, float* __restrict__ out,
                          const int* __restrict__ src, const int* __restrict__ dst,
                          const float* __restrict__ dinv, int E)
{
    int warp = (blockIdx.x * blockDim.x + threadIdx.x) >> 5;
    int lane = threadIdx.x & 31;
    if (warp >= E) return;

    int   s = __ldg(&src[warp]);
    int   d = __ldg(&dst[warp]);
    float w = __ldg(&dinv[d]);

    float4 v = __ldg((const float4*)(ts + (size_t)s * 128) + lane);
    v.x *= w; v.y *= w; v.z *= w; v.w *= w;

    float* p = out + (size_t)d * 128 + lane * 4;
    asm volatile("red.global.add.v4.f32 [%0], {%1,%2,%3,%4};"
                 :: "l"(p), "f"(v.x), "f"(v.y), "f"(v.z), "f"(v.w)
                 : "memory");
}

// ---------------------------------------------------------------------------

extern "C" void kernel_launch(void* const* d_in, const int* in_sizes, int n_in,
                              void* d_out, int out_size)
{
    const float* x   = (const float*)d_in[0];
    const int*   ei  = (const int*)  d_in[1];
    const float* W1  = (const float*)d_in[2];
    const float* b1  = (const float*)d_in[3];
    const float* Wmu = (const float*)d_in[4];
    const float* bmu = (const float*)d_in[5];
    const float* Wls = (const float*)d_in[6];
    const float* bls = (const float*)d_in[7];

    const int N = in_sizes[0] / 256;   // C_in = 256
    const int E = in_sizes[1] / 2;
    const int* src = ei;
    const int* dst = ei + E;

    float* out = (float*)d_out;
    float* mu  = out;                          // [N,128]
    float* ls  = out + (size_t)N * HDIM;       // [N,128]

    float *deg, *dinv, *ts1, *out1, *ts2;
    cudaGetSymbolAddress((void**)&deg,  g_deg);
    cudaGetSymbolAddress((void**)&dinv, g_dinv);
    cudaGetSymbolAddress((void**)&ts1,  g_ts1);
    cudaGetSymbolAddress((void**)&out1, g_out1);
    cudaGetSymbolAddress((void**)&ts2,  g_ts2);
    float* ts2b = ts2 + (size_t)N * HDIM;

    const int nb = (N + 255) / 256;
    const int eb = (E + 255) / 256;
    const int gb = (N + 127) / 128;
    const int sb = (int)(((long long)E * 32 + 255) / 256);

    // degree + dinv (recomputed every replay; deg must be re-zeroed)
    k_zero <<<nb, 256>>>(deg, N);
    k_count<<<eb, 256>>>(dst, deg, E);
    k_dinv <<<nb, 256>>>(deg, dinv, N);

    // layer 1: ts1 = (x@W1)*dinv ; out1 = ts1*dinv + b1 ; out1[dst] += ts1[src]*dinv[dst]
    k_gemm128<<<gb, 256>>>(x, W1, b1, dinv, ts1, out1, N, 256, 0);
    k_scatter<<<sb, 256>>>(ts1, out1, src, dst, dinv, E);

    // layer 2 heads (ReLU fused into A load); init written straight into d_out
    k_gemm128<<<gb, 256>>>(out1, Wmu, bmu, dinv, ts2,  mu, N, 128, 1);
    k_gemm128<<<gb, 256>>>(out1, Wls, bls, dinv, ts2b, ls, N, 128, 1);
    k_scatter<<<sb, 256>>>(ts2,  mu, src, dst, dinv, E);
    k_scatter<<<sb, 256>>>(ts2b, ls, src, dst, dinv, E);
}

// round 3
// speedup vs baseline: 3.0701x; 3.0701x over previous
#include <cuda_runtime.h>
#include <cstdint>

// ---------------------------------------------------------------------------
// Stochastic_encoder (VGAE GCN encoder), fp32, CSR gather-aggregation.
//   deg/dinv ; CSR(dst) built once, reused for all 3 aggregations
//   ts1 = (x@W1)*dinv[row]
//   h   = relu(dinv*(ts1[self] + sum_src ts1[src]) + b1)      [gather, no atomics]
//   ts2[:, 0:128]   = (h@Wmu)*dinv ; ts2[:,128:256] = (h@Wls)*dinv
//   mu/ls = dinv*(ts2[self] + sum ts2[src]) + b               [one 256-wide gather]
// ---------------------------------------------------------------------------

#define NMAX 50176
#define EMAX 800000
#define HDIM 128
#define SCAN_B 1024

__device__ int   g_deg   [NMAX];
__device__ int   g_base  [NMAX];
__device__ int   g_cursor[NMAX];
__device__ int   g_part  [256];
__device__ int   g_adj   [EMAX];
__device__ float g_dinv  [NMAX];
__device__ float g_ts1   [(size_t)NMAX * HDIM];
__device__ float g_h     [(size_t)NMAX * HDIM];
__device__ float g_ts2   [(size_t)NMAX * 2 * HDIM];

// ---------------------------------------------------------------------------

__global__ void k_zero_int(int* __restrict__ p, int n) {
    int i = blockIdx.x * blockDim.x + threadIdx.x;
    if (i < n) p[i] = 0;
}

__global__ void k_count(const int* __restrict__ dst, int* __restrict__ deg, int E) {
    int i = blockIdx.x * blockDim.x + threadIdx.x;
    if (i < E) atomicAdd(&deg[dst[i]], 1);
}

__global__ void k_dinv(const int* __restrict__ deg, float* __restrict__ dinv, int n) {
    int i = blockIdx.x * blockDim.x + threadIdx.x;
    if (i < n) dinv[i] = rsqrtf((float)deg[i] + 1.0f);
}

// --- 3-kernel exclusive scan of deg -> base -------------------------------
__global__ void k_scan_block(const int* __restrict__ deg, int* __restrict__ base,
                             int* __restrict__ part, int n)
{
    __shared__ int sh[SCAN_B];
    int gi = blockIdx.x * SCAN_B + threadIdx.x;
    int v = (gi < n) ? deg[gi] : 0;
    sh[threadIdx.x] = v;
    __syncthreads();
    // inclusive Hillis-Steele
    #pragma unroll
    for (int off = 1; off < SCAN_B; off <<= 1) {
        int t = (threadIdx.x >= off) ? sh[threadIdx.x - off] : 0;
        __syncthreads();
        sh[threadIdx.x] += t;
        __syncthreads();
    }
    if (gi < n) base[gi] = sh[threadIdx.x] - v;   // exclusive
    if (threadIdx.x == SCAN_B - 1) part[blockIdx.x] = sh[threadIdx.x];
}

__global__ void k_scan_part(int* __restrict__ part, int nb) {
    if (threadIdx.x == 0) {
        int acc = 0;
        for (int i = 0; i < nb; i++) { int v = part[i]; part[i] = acc; acc += v; }
    }
}

__global__ void k_scan_add(int* __restrict__ base, const int* __restrict__ part, int n) {
    int gi = blockIdx.x * SCAN_B + threadIdx.x;
    if (gi < n) base[gi] += part[blockIdx.x];
}

__global__ void k_fill(const int* __restrict__ src, const int* __restrict__ dst,
                       const int* __restrict__ base, int* __restrict__ cursor,
                       int* __restrict__ adj, int E)
{
    int i = blockIdx.x * blockDim.x + threadIdx.x;
    if (i < E) {
        int d = dst[i];
        int pos = base[d] + atomicAdd(&cursor[d], 1);
        adj[pos] = src[i];
    }
}

// ---------------------------------------------------------------------------
// Tiled SGEMM: ts[r, coloff + c] = (A[N,K] @ W[K,128])[r,c] * dinv[r]
// BM=128, BN=128, BK=32, 256 threads, 8x8 micro-tile; ts has row stride ldts.
// ---------------------------------------------------------------------------
__global__ __launch_bounds__(256, 2)
void k_gemm128(const float* __restrict__ A, const float* __restrict__ W,
               const float* __restrict__ dinv, float* __restrict__ ts,
               int N, int K, int ldts, int coloff)
{
    __shared__ float As[32][129];
    __shared__ float Bs[32][128];

    const int tid  = threadIdx.x;
    const int tx   = tid & 15;
    const int ty   = tid >> 4;
    const int row0 = blockIdx.x * 128;

    float acc[8][8];
    #pragma unroll
    for (int i = 0; i < 8; i++)
        #pragma unroll
        for (int j = 0; j < 8; j++) acc[i][j] = 0.0f;

    for (int k0 = 0; k0 < K; k0 += 32) {
        {
            const int c  = tid & 7;
            const int m0 = tid >> 3;
            #pragma unroll
            for (int p = 0; p < 4; p++) {
                int m = m0 + 32 * p;
                int r = row0 + m;
                float4 v = make_float4(0.f, 0.f, 0.f, 0.f);
                if (r < N)
                    v = *(const float4*)(A + (size_t)r * K + (k0 + c * 4));
                As[c * 4 + 0][m] = v.x;
                As[c * 4 + 1][m] = v.y;
                As[c * 4 + 2][m] = v.z;
                As[c * 4 + 3][m] = v.w;
            }
        }
        {
            const int cb  = tid & 31;
            const int kr0 = tid >> 5;
            #pragma unroll
            for (int p = 0; p < 4; p++) {
                int kr = kr0 + 8 * p;
                *(float4*)&Bs[kr][cb * 4] =
                    *(const float4*)(W + (size_t)(k0 + kr) * 128 + cb * 4);
            }
        }
        __syncthreads();

        #pragma unroll
        for (int kk = 0; kk < 32; kk++) {
            float a[8], b[8];
            #pragma unroll
            for (int i = 0; i < 8; i++) a[i] = As[kk][ty * 8 + i];
            float4 b0 = *(float4*)&Bs[kk][tx * 8];
            float4 b1 = *(float4*)&Bs[kk][tx * 8 + 4];
            b[0] = b0.x; b[1] = b0.y; b[2] = b0.z; b[3] = b0.w;
            b[4] = b1.x; b[5] = b1.y; b[6] = b1.z; b[7] = b1.w;
            #pragma unroll
            for (int i = 0; i < 8; i++)
                #pragma unroll
                for (int j = 0; j < 8; j++)
                    acc[i][j] = fmaf(a[i], b[j], acc[i][j]);
        }
        __syncthreads();
    }

    #pragma unroll
    for (int i = 0; i < 8; i++) {
        int r = row0 + ty * 8 + i;
        if (r < N) {
            float di = dinv[r];
            float* dst = ts + (size_t)r * ldts + coloff + tx * 8;
            float4 o0, o1;
            o0.x = acc[i][0] * di; o0.y = acc[i][1] * di;
            o0.z = acc[i][2] * di; o0.w = acc[i][3] * di;
            o1.x = acc[i][4] * di; o1.y = acc[i][5] * di;
            o1.z = acc[i][6] * di; o1.w = acc[i][7] * di;
            *(float4*)dst       = o0;
            *(float4*)(dst + 4) = o1;
        }
    }
}

// ---------------------------------------------------------------------------
// Gather-aggregation, 128 wide (layer 1): warp per node.
//   h[d] = relu( dinv[d]*(ts[d] + sum_{s in adj(d)} ts[s]) + b )
// ---------------------------------------------------------------------------
__global__ __launch_bounds__(256)
void k_agg128(const float* __restrict__ ts, const int* __restrict__ adj,
              const int* __restrict__ base, const int* __restrict__ deg,
              const float* __restrict__ dinv, const float* __restrict__ b,
              float* __restrict__ h, int N)
{
    int node = (blockIdx.x * blockDim.x + threadIdx.x) >> 5;
    int lane = threadIdx.x & 31;
    if (node >= N) return;

    float4 acc = __ldg((const float4*)(ts + (size_t)node * 128) + lane);  // self
    int e0 = base[node], cnt = deg[node];

    for (int eb = 0; eb < cnt; eb += 32) {
        int rem = cnt - eb;
        int myidx = (lane < rem) ? __ldg(&adj[e0 + eb + lane]) : 0;
        int m = rem < 32 ? rem : 32;
        for (int j = 0; j < m; j++) {
            int s = __shfl_sync(0xffffffffu, myidx, j);
            float4 v = __ldg((const float4*)(ts + (size_t)s * 128) + lane);
            acc.x += v.x; acc.y += v.y; acc.z += v.z; acc.w += v.w;
        }
    }

    float di = dinv[node];
    float4 bb = __ldg((const float4*)b + lane);
    float4 o;
    o.x = fmaxf(fmaf(acc.x, di, bb.x), 0.f);
    o.y = fmaxf(fmaf(acc.y, di, bb.y), 0.f);
    o.z = fmaxf(fmaf(acc.z, di, bb.z), 0.f);
    o.w = fmaxf(fmaf(acc.w, di, bb.w), 0.f);
    ((float4*)(h + (size_t)node * 128))[lane] = o;
}

// ---------------------------------------------------------------------------
// Gather-aggregation, 256 wide (mu || logstd): warp per node, 8 floats/lane.
// ---------------------------------------------------------------------------
__global__ __launch_bounds__(256)
void k_agg256(const float* __restrict__ ts2, const int* __restrict__ adj,
              const int* __restrict__ base, const int* __restrict__ deg,
              const float* __restrict__ dinv,
              const float* __restrict__ bmu, const float* __restrict__ bls,
              float* __restrict__ mu, float* __restrict__ ls, int N)
{
    int node = (blockIdx.x * blockDim.x + threadIdx.x) >> 5;
    int lane = threadIdx.x & 31;
    if (node >= N) return;

    const float4* self = (const float4*)(ts2 + (size_t)node * 256);
    float4 am = __ldg(self + lane);        // mu cols
    float4 al = __ldg(self + 32 + lane);   // ls cols
    int e0 = base[node], cnt = deg[node];

    for (int eb = 0; eb < cnt; eb += 32) {
        int rem = cnt - eb;
        int myidx = (lane < rem) ? __ldg(&adj[e0 + eb + lane]) : 0;
        int m = rem < 32 ? rem : 32;
        for (int j = 0; j < m; j++) {
            int s = __shfl_sync(0xffffffffu, myidx, j);
            const float4* row = (const float4*)(ts2 + (size_t)s * 256);
            float4 vm = __ldg(row + lane);
            float4 vl = __ldg(row + 32 + lane);
            am.x += vm.x; am.y += vm.y; am.z += vm.z; am.w += vm.w;
            al.x += vl.x; al.y += vl.y; al.z += vl.z; al.w += vl.w;
        }
    }

    float di = dinv[node];
    float4 bm = __ldg((const float4*)bmu + lane);
    float4 bl = __ldg((const float4*)bls + lane);
    float4 om, ol;
    om.x = fmaf(am.x, di, bm.x); om.y = fmaf(am.y, di, bm.y);
    om.z = fmaf(am.z, di, bm.z); om.w = fmaf(am.w, di, bm.w);
    ol.x = fmaf(al.x, di, bl.x); ol.y = fmaf(al.y, di, bl.y);
    ol.z = fmaf(al.z, di, bl.z); ol.w = fmaf(al.w, di, bl.w);
    ((float4*)(mu + (size_t)node * 128))[lane] = om;
    ((float4*)(ls + (size_t)node * 128))[lane] = ol;
}

// ---------------------------------------------------------------------------

extern "C" void kernel_launch(void* const* d_in, const int* in_sizes, int n_in,
                              void* d_out, int out_size)
{
    const float* x   = (const float*)d_in[0];
    const int*   ei  = (const int*)  d_in[1];
    const float* W1  = (const float*)d_in[2];
    const float* b1  = (const float*)d_in[3];
    const float* Wmu = (const float*)d_in[4];
    const float* bmu = (const float*)d_in[5];
    const float* Wls = (const float*)d_in[6];
    const float* bls = (const float*)d_in[7];

    const int N = in_sizes[0] / 256;   // C_in = 256
    const int E = in_sizes[1] / 2;
    const int* src = ei;
    const int* dst = ei + E;

    float* out = (float*)d_out;
    float* mu  = out;
    float* ls  = out + (size_t)N * HDIM;

    int *deg, *base, *cursor, *part, *adj;
    float *dinv, *ts1, *h, *ts2;
    cudaGetSymbolAddress((void**)&deg,    g_deg);
    cudaGetSymbolAddress((void**)&base,   g_base);
    cudaGetSymbolAddress((void**)&cursor, g_cursor);
    cudaGetSymbolAddress((void**)&part,   g_part);
    cudaGetSymbolAddress((void**)&adj,    g_adj);
    cudaGetSymbolAddress((void**)&dinv,   g_dinv);
    cudaGetSymbolAddress((void**)&ts1,    g_ts1);
    cudaGetSymbolAddress((void**)&h,      g_h);
    cudaGetSymbolAddress((void**)&ts2,    g_ts2);

    const int nb   = (N + 255) / 256;
    const int eb   = (E + 255) / 256;
    const int gb   = (N + 127) / 128;
    const int sbnk = (N + SCAN_B - 1) / SCAN_B;
    const int ab   = (N * 32 + 255) / 256;   // warp per node

    // degree + dinv + CSR (reused by all 3 aggregations)
    k_zero_int<<<nb, 256>>>(deg, N);
    k_zero_int<<<nb, 256>>>(cursor, N);
    k_count   <<<eb, 256>>>(dst, deg, E);
    k_dinv    <<<nb, 256>>>(deg, dinv, N);
    k_scan_block<<<sbnk, SCAN_B>>>(deg, base, part, N);
    k_scan_part <<<1, 32>>>(part, sbnk);
    k_scan_add  <<<sbnk, SCAN_B>>>(base, part, N);
    k_fill      <<<eb, 256>>>(src, dst, base, cursor, adj, E);

    // layer 1
    k_gemm128<<<gb, 256>>>(x, W1, dinv, ts1, N, 256, 128, 0);
    k_agg128 <<<ab, 256>>>(ts1, adj, base, deg, dinv, b1, h, N);

    // layer 2 heads into ts2[N,256], then one merged aggregation
    k_gemm128<<<gb, 256>>>(h, Wmu, dinv, ts2, N, 128, 256, 0);
    k_gemm128<<<gb, 256>>>(h, Wls, dinv, ts2, N, 128, 256, 128);
    k_agg256 <<<ab, 256>>>(ts2, adj, base, deg, dinv, bmu, bls, mu, ls, N);
}